// round 12
// baseline (speedup 1.0000x reference)
#include <cuda_runtime.h>

#define S 512
#define D 512
#define H 8
#define HD 64
#define NE 1024

// ---- scratch ----
__device__ float g_q[S * D];
__device__ float g_k[S * D];
__device__ float g_v[S * D];
__device__ float g_rkt[NE * D];
__device__ float g_rqt[NE * D];
__device__ float g_ctx[S * D];
__device__ float g_A[H * S * S];    // q·k     [h,i,j]
__device__ float g_B[H * S * NE];   // q·rkt   [h,i,e]
__device__ float g_C[H * NE * S];   // rqt·k   [h,e,j]
__device__ float g_Cd[H * S * S];   // Sc in diagonal (attn) layout

__device__ __forceinline__ unsigned f2tf32(float x) {
    unsigned r;
    asm("cvt.rna.tf32.f32 %0, %1;" : "=r"(r) : "f"(x));
    return r;
}

#define MMA8(c, a, b) \
    asm volatile("mma.sync.aligned.m16n8k8.row.col.f32.tf32.tf32.f32 " \
                 "{%0,%1,%2,%3},{%4,%5,%6,%7},{%8,%9},{%0,%1,%2,%3};" \
                 : "+f"((c)[0]), "+f"((c)[1]), "+f"((c)[2]), "+f"((c)[3]) \
                 : "r"((a)[0]), "r"((a)[1]), "r"((a)[2]), "r"((a)[3]), \
                   "r"((b)[0]), "r"((b)[1]))

// ============================================================
// proj (tf32 mma): fused 5-way projection. 128x128 tile, 256 thr.
// ============================================================
__global__ __launch_bounds__(256) void proj_tf32_kernel(
        const float* __restrict__ hs, const float* __restrict__ emb,
        const float* __restrict__ wq, const float* __restrict__ bq,
        const float* __restrict__ wk, const float* __restrict__ bk,
        const float* __restrict__ wv, const float* __restrict__ bv,
        const float* __restrict__ wrk, const float* __restrict__ brk,
        const float* __restrict__ wrq, const float* __restrict__ brq,
        float* __restrict__ q, float* __restrict__ k, float* __restrict__ v,
        float* __restrict__ rkt, float* __restrict__ rqt) {
    const float *A, *W, *bias; float* Cm; int M;
    switch (blockIdx.z) {
        case 0: A = hs;  W = wq;  bias = bq;  Cm = q;   M = S;  break;
        case 1: A = hs;  W = wk;  bias = bk;  Cm = k;   M = S;  break;
        case 2: A = hs;  W = wv;  bias = bv;  Cm = v;   M = S;  break;
        case 3: A = emb; W = wrk; bias = brk; Cm = rkt; M = NE; break;
        default:A = emb; W = wrq; bias = brq; Cm = rqt; M = NE; break;
    }
    const int m0 = blockIdx.y * 128, n0 = blockIdx.x * 128;
    if (m0 >= M) return;

    __shared__ unsigned As[2][16][136];
    __shared__ unsigned Bs[2][16][136];

    const int tid = threadIdx.x;
    const int r0 = tid >> 2;
    const int c4 = (tid & 3) * 4;
    const int w = tid >> 5, lane = tid & 31;
    const int g = lane >> 2, tig = lane & 3;
    const int wm = w >> 1, wn = w & 1;

    const float* Ar0 = A + (size_t)(m0 + r0) * D + c4;
    const float* Ar1 = A + (size_t)(m0 + 64 + r0) * D + c4;
    const float* Wr0 = W + (size_t)(n0 + r0) * D + c4;
    const float* Wr1 = W + (size_t)(n0 + 64 + r0) * D + c4;

    float4 pa0, pa1, pb0, pb1;

#define PGLOAD(K0) do { \
        pa0 = *(const float4*)(Ar0 + (K0)); \
        pa1 = *(const float4*)(Ar1 + (K0)); \
        pb0 = *(const float4*)(Wr0 + (K0)); \
        pb1 = *(const float4*)(Wr1 + (K0)); } while (0)

#define PGSTORE(BUF) do { \
        As[BUF][c4 + 0][r0] = f2tf32(pa0.x); As[BUF][c4 + 1][r0] = f2tf32(pa0.y); \
        As[BUF][c4 + 2][r0] = f2tf32(pa0.z); As[BUF][c4 + 3][r0] = f2tf32(pa0.w); \
        As[BUF][c4 + 0][64 + r0] = f2tf32(pa1.x); As[BUF][c4 + 1][64 + r0] = f2tf32(pa1.y); \
        As[BUF][c4 + 2][64 + r0] = f2tf32(pa1.z); As[BUF][c4 + 3][64 + r0] = f2tf32(pa1.w); \
        Bs[BUF][c4 + 0][r0] = f2tf32(pb0.x); Bs[BUF][c4 + 1][r0] = f2tf32(pb0.y); \
        Bs[BUF][c4 + 2][r0] = f2tf32(pb0.z); Bs[BUF][c4 + 3][r0] = f2tf32(pb0.w); \
        Bs[BUF][c4 + 0][64 + r0] = f2tf32(pb1.x); Bs[BUF][c4 + 1][64 + r0] = f2tf32(pb1.y); \
        Bs[BUF][c4 + 2][64 + r0] = f2tf32(pb1.z); Bs[BUF][c4 + 3][64 + r0] = f2tf32(pb1.w); } while (0)

    float c[2][8][4];
#pragma unroll
    for (int mt = 0; mt < 2; mt++)
#pragma unroll
        for (int nt = 0; nt < 8; nt++)
#pragma unroll
            for (int r = 0; r < 4; r++) c[mt][nt][r] = 0.f;

    PGLOAD(0);
    PGSTORE(0);
    __syncthreads();

    int buf = 0;
    for (int k0 = 0; k0 < D; k0 += 16) {
        const bool more = (k0 + 16 < D);
        if (more) PGLOAD(k0 + 16);
#pragma unroll
        for (int ks = 0; ks < 16; ks += 8) {
            const int kb = ks + tig;
            unsigned a[2][4], b[8][2];
#pragma unroll
            for (int mt = 0; mt < 2; mt++) {
                const int ma = wm * 32 + mt * 16 + g;
                a[mt][0] = As[buf][kb][ma];
                a[mt][1] = As[buf][kb][ma + 8];
                a[mt][2] = As[buf][kb + 4][ma];
                a[mt][3] = As[buf][kb + 4][ma + 8];
            }
#pragma unroll
            for (int nt = 0; nt < 8; nt++) {
                const int nb = wn * 64 + nt * 8 + g;
                b[nt][0] = Bs[buf][kb][nb];
                b[nt][1] = Bs[buf][kb + 4][nb];
            }
#pragma unroll
            for (int mt = 0; mt < 2; mt++)
#pragma unroll
                for (int nt = 0; nt < 8; nt++) MMA8(c[mt][nt], a[mt], b[nt]);
        }
        if (more) {
            buf ^= 1;
            PGSTORE(buf);
            __syncthreads();
        }
    }

#pragma unroll
    for (int mt = 0; mt < 2; mt++) {
        const int r = m0 + wm * 32 + mt * 16 + g;
#pragma unroll
        for (int nt = 0; nt < 8; nt++) {
            const int col = n0 + wn * 64 + nt * 8 + 2 * tig;
            const float b0v = bias[col], b1v = bias[col + 1];
            *(float2*)(Cm + (size_t)r * D + col) =
                make_float2(c[mt][nt][0] + b0v, c[mt][nt][1] + b1v);
            *(float2*)(Cm + (size_t)(r + 8) * D + col) =
                make_float2(c[mt][nt][2] + b0v, c[mt][nt][3] + b1v);
        }
    }
#undef PGLOAD
#undef PGSTORE
}

// ============================================================
// 64x64 tf32 mma core (128 thr), shared by scores and out-proj.
// ============================================================
__device__ __forceinline__ void gemm64_tf32_core(
        const float* __restrict__ A, int lda,
        const float* __restrict__ B, int ldb,
        float* __restrict__ Cm, int ldc,
        const float* __restrict__ bias,
        int m0, int n0, int K,
        unsigned (*As)[72], unsigned (*Bs)[72]) {
    const int tid = threadIdx.x;
    const int w = tid >> 5, lane = tid & 31;
    const int g = lane >> 2, tig = lane & 3;
    const int wm = w >> 1, wn = w & 1;
    const int lm = tid >> 1;
    const int lk8 = (tid & 1) * 8;

    float c[2][4][4];
#pragma unroll
    for (int mt = 0; mt < 2; mt++)
#pragma unroll
        for (int nt = 0; nt < 4; nt++)
#pragma unroll
            for (int r = 0; r < 4; r++) c[mt][nt][r] = 0.f;

    for (int k0 = 0; k0 < K; k0 += 16) {
        float4 xa = *(const float4*)(A + (size_t)(m0 + lm) * lda + k0 + lk8);
        float4 ya = *(const float4*)(A + (size_t)(m0 + lm) * lda + k0 + lk8 + 4);
        float4 xb = *(const float4*)(B + (size_t)(n0 + lm) * ldb + k0 + lk8);
        float4 yb = *(const float4*)(B + (size_t)(n0 + lm) * ldb + k0 + lk8 + 4);
        As[lk8 + 0][lm] = f2tf32(xa.x); As[lk8 + 1][lm] = f2tf32(xa.y);
        As[lk8 + 2][lm] = f2tf32(xa.z); As[lk8 + 3][lm] = f2tf32(xa.w);
        As[lk8 + 4][lm] = f2tf32(ya.x); As[lk8 + 5][lm] = f2tf32(ya.y);
        As[lk8 + 6][lm] = f2tf32(ya.z); As[lk8 + 7][lm] = f2tf32(ya.w);
        Bs[lk8 + 0][lm] = f2tf32(xb.x); Bs[lk8 + 1][lm] = f2tf32(xb.y);
        Bs[lk8 + 2][lm] = f2tf32(xb.z); Bs[lk8 + 3][lm] = f2tf32(xb.w);
        Bs[lk8 + 4][lm] = f2tf32(yb.x); Bs[lk8 + 5][lm] = f2tf32(yb.y);
        Bs[lk8 + 6][lm] = f2tf32(yb.z); Bs[lk8 + 7][lm] = f2tf32(yb.w);
        __syncthreads();
#pragma unroll
        for (int ks = 0; ks < 16; ks += 8) {
            const int kb = ks + tig;
            unsigned a[2][4], b[4][2];
#pragma unroll
            for (int mt = 0; mt < 2; mt++) {
                const int ma = wm * 32 + mt * 16 + g;
                a[mt][0] = As[kb][ma];
                a[mt][1] = As[kb][ma + 8];
                a[mt][2] = As[kb + 4][ma];
                a[mt][3] = As[kb + 4][ma + 8];
            }
#pragma unroll
            for (int nt = 0; nt < 4; nt++) {
                const int nb = wn * 32 + nt * 8 + g;
                b[nt][0] = Bs[kb][nb];
                b[nt][1] = Bs[kb + 4][nb];
            }
#pragma unroll
            for (int mt = 0; mt < 2; mt++)
#pragma unroll
                for (int nt = 0; nt < 4; nt++) MMA8(c[mt][nt], a[mt], b[nt]);
        }
        __syncthreads();
    }

#pragma unroll
    for (int mt = 0; mt < 2; mt++) {
        const int r = m0 + wm * 32 + mt * 16 + g;
#pragma unroll
        for (int nt = 0; nt < 4; nt++) {
            const int col = n0 + wn * 32 + nt * 8 + 2 * tig;
            float b0v = 0.f, b1v = 0.f;
            if (bias) { b0v = bias[col]; b1v = bias[col + 1]; }
            *(float2*)(Cm + (size_t)r * ldc + col) =
                make_float2(c[mt][nt][0] + b0v, c[mt][nt][1] + b1v);
            *(float2*)(Cm + (size_t)(r + 8) * ldc + col) =
                make_float2(c[mt][nt][2] + b0v, c[mt][nt][3] + b1v);
        }
    }
}

// ============================================================
// scores (tf32): merged A/B/C head GEMMs, 64x64 tiles, pruned.
// ============================================================
__global__ __launch_bounds__(128) void scores_tf32_kernel(
        const float* __restrict__ qf, const float* __restrict__ kf,
        const float* __restrict__ rkt, const float* __restrict__ rqt,
        float* __restrict__ Sa, float* __restrict__ Sb, float* __restrict__ Sc) {
    const int h = blockIdx.y;
    int bi = blockIdx.x;
    const float *A, *B; float* Cm; int m0, n0, ldc;

    if (bi < 64) {
        m0 = (bi >> 3) * 64; n0 = (bi & 7) * 64;
        A = qf; B = kf; Cm = Sa + (size_t)h * S * S; ldc = S;
    } else if (bi < 192) {
        bi -= 64;
        m0 = (bi >> 4) * 64; n0 = (bi & 15) * 64;
        const int sum = m0 + n0;
        if (sum + 126 < 512 || sum > 1023) return;
        A = qf; B = rkt; Cm = Sb + (size_t)h * S * NE; ldc = NE;
    } else {
        bi -= 192;
        m0 = (bi >> 3) * 64; n0 = (bi & 7) * 64;
        const int d = m0 - n0;
        if (d < 0 || d > 512) return;
        A = rqt; B = kf; Cm = Sc + (size_t)h * NE * S; ldc = S;
    }
    A += h * HD; B += h * HD;

    __shared__ unsigned As[16][72];
    __shared__ unsigned Bs[16][72];
    gemm64_tf32_core(A, D, B, D, Cm, ldc, nullptr, m0, n0, HD, As, Bs);
}

// ============================================================
// cdiag: smem-transpose Sc live tiles onto diagonal layout
// Cd[h,i,j] = Sc[h, j-i+512, j].
// ============================================================
__global__ __launch_bounds__(256) void cdiag_kernel(const float* __restrict__ Cm,
                                                    float* __restrict__ Cd) {
    const int h = blockIdx.y;
    const int tj = blockIdx.x / 9, r = blockIdx.x % 9;
    const int te = tj + r;
    const int e0 = te * 64, j0 = tj * 64;
    const int ib = 512 + j0 - e0;

    __shared__ float t[64][65];
    const int tid = threadIdx.x;
    const int lr = tid >> 4;
    const int lc4 = (tid & 15) * 4;
#pragma unroll
    for (int rr = 0; rr < 64; rr += 16) {
        float4 v = *(const float4*)(Cm + ((size_t)h * NE + e0 + rr + lr) * S + j0 + lc4);
        t[rr + lr][lc4 + 0] = v.x; t[rr + lr][lc4 + 1] = v.y;
        t[rr + lr][lc4 + 2] = v.z; t[rr + lr][lc4 + 3] = v.w;
    }
    __syncthreads();

    const int sub = tid >> 6;
    const int lj = tid & 63;
#pragma unroll 4
    for (int rr = 0; rr < 128; rr += 4) {
        const int dd = rr + sub - 63;
        const int i = ib + dd;
        if (i >= 0 && i < S && lj >= dd && lj <= 63 + dd) {
            const int le = lj - dd;
            Cd[((size_t)h * S + i) * S + j0 + lj] = t[le][lj];
        }
    }
}

// ============================================================
// out-proj (tf32): out = ctx @ wo^T + bo, 64x64 tiles, K=512.
// ============================================================
__global__ __launch_bounds__(128) void out_tf32_kernel(
        const float* __restrict__ ctx, const float* __restrict__ wo,
        const float* __restrict__ bo, float* __restrict__ out) {
    __shared__ unsigned As[16][72];
    __shared__ unsigned Bs[16][72];
    gemm64_tf32_core(ctx, D, wo, D, out, D, bo,
                     blockIdx.y * 64, blockIdx.x * 64, D, As, Bs);
}

// ============================================================
// FUSED softmax + ctx. Block = (16-row i-tile, h), 128 threads.
// Phase 1: warp-quad softmax -> attn (global, required output)
//          and smem tile (A-matrix of the ctx GEMM).
// Phase 2: ctx[i, h*64+c] = attn_smem[16x512] @ v_h[512x64],
//          v streamed via smem in 32-row chunks; 2x4 accs/thr.
// Replaces softmax_warp + ctx_part + reduce8 (one launch, no
// part buffer, no attn re-read).
// ============================================================
#define SA_LD 516   // row stride: 16B-aligned rows, 2-way max bank conflict

__global__ __launch_bounds__(128) void smax_ctx_kernel(
        const float* __restrict__ Asc, const float* __restrict__ Bm,
        const float* __restrict__ Cd, const float* __restrict__ vf,
        float* __restrict__ attn, float* __restrict__ ctx) {
    const int h = blockIdx.y;
    const int i0 = blockIdx.x * 16;

    __shared__ float sa[16][SA_LD];   // 33 KB attn tile
    __shared__ float sv[32][68];      // 8.7 KB v chunk

    const int tid = threadIdx.x;
    const int warp = tid >> 5, lane = tid & 31;

    // ---------- phase 1: softmax (each warp: 4 rows) ----------
#pragma unroll
    for (int rr = 0; rr < 4; rr++) {
        const int i = i0 + warp * 4 + rr;
        const float* aRow = Asc + ((size_t)h * S + i) * S;
        const float* bRow = Bm + ((size_t)h * S + i) * NE + (512 - i);
        const float* cRow = Cd + ((size_t)h * S + i) * S;
        const int jb = lane * 16;   // 16 contiguous j per lane

        float sc[16];
#pragma unroll
        for (int t = 0; t < 4; t++) {
            const int j = jb + t * 4;
            float4 av = *(const float4*)(aRow + j);
            float4 cv = *(const float4*)(cRow + j);
            sc[t * 4 + 0] = (av.x + cv.x + bRow[j + 0]) * 0.125f;
            sc[t * 4 + 1] = (av.y + cv.y + bRow[j + 1]) * 0.125f;
            sc[t * 4 + 2] = (av.z + cv.z + bRow[j + 2]) * 0.125f;
            sc[t * 4 + 3] = (av.w + cv.w + bRow[j + 3]) * 0.125f;
        }

        float mx = sc[0];
#pragma unroll
        for (int t = 1; t < 16; t++) mx = fmaxf(mx, sc[t]);
#pragma unroll
        for (int o = 16; o; o >>= 1) mx = fmaxf(mx, __shfl_xor_sync(0xffffffffu, mx, o));

        float sum = 0.f;
#pragma unroll
        for (int t = 0; t < 16; t++) {
            sc[t] = __expf(sc[t] - mx);
            sum += sc[t];
        }
#pragma unroll
        for (int o = 16; o; o >>= 1) sum += __shfl_xor_sync(0xffffffffu, sum, o);
        const float inv = 1.f / sum;

        const int lrow = warp * 4 + rr;
        float* gRow = attn + ((size_t)h * S + i) * S;
#pragma unroll
        for (int t = 0; t < 4; t++) {
            float4 r = make_float4(sc[t * 4 + 0] * inv, sc[t * 4 + 1] * inv,
                                   sc[t * 4 + 2] * inv, sc[t * 4 + 3] * inv);
            *(float4*)&sa[lrow][jb + t * 4] = r;
            *(float4*)(gRow + jb + t * 4) = r;
        }
    }
    __syncthreads();

    // ---------- phase 2: ctx GEMM ----------
    const int ty = tid >> 4, tx = tid & 15;   // 8 x 16: 2 rows x 4 cols per thread
    float acc[2][4];
#pragma unroll
    for (int r = 0; r < 2; r++)
#pragma unroll
        for (int cc = 0; cc < 4; cc++) acc[r][cc] = 0.f;

#pragma unroll 1
    for (int kc = 0; kc < S; kc += 32) {
        // load v chunk [32 x 64] (coalesced float4)
#pragma unroll
        for (int p = 0; p < 4; p++) {
            const int f = p * 128 + tid;          // 0..511 float4 slots
            const int r = f >> 4, cc = (f & 15) * 4;
            *(float4*)&sv[r][cc] =
                *(const float4*)(vf + (size_t)(kc + r) * D + h * HD + cc);
        }
        __syncthreads();
#pragma unroll
        for (int kk = 0; kk < 32; kk++) {
            const float a0 = sa[ty * 2 + 0][kc + kk];
            const float a1 = sa[ty * 2 + 1][kc + kk];
            float4 b = *(const float4*)&sv[kk][tx * 4];
            acc[0][0] += a0 * b.x; acc[0][1] += a0 * b.y;
            acc[0][2] += a0 * b.z; acc[0][3] += a0 * b.w;
            acc[1][0] += a1 * b.x; acc[1][1] += a1 * b.y;
            acc[1][2] += a1 * b.z; acc[1][3] += a1 * b.w;
        }
        __syncthreads();
    }

#pragma unroll
    for (int r = 0; r < 2; r++) {
        const int i = i0 + ty * 2 + r;
        *(float4*)(ctx + (size_t)i * D + h * HD + tx * 4) =
            make_float4(acc[r][0], acc[r][1], acc[r][2], acc[r][3]);
    }
}

extern "C" void kernel_launch(void* const* d_in, const int* in_sizes, int n_in,
                              void* d_out, int out_size) {
    const float* hs  = (const float*)d_in[0];
    const float* emb = (const float*)d_in[1];
    const float* wq  = (const float*)d_in[2];
    const float* bq  = (const float*)d_in[3];
    const float* wk  = (const float*)d_in[4];
    const float* bk  = (const float*)d_in[5];
    const float* wv  = (const float*)d_in[6];
    const float* bv  = (const float*)d_in[7];
    const float* wrk = (const float*)d_in[8];
    const float* brk = (const float*)d_in[9];
    const float* wrq = (const float*)d_in[10];
    const float* brq = (const float*)d_in[11];
    const float* wo  = (const float*)d_in[12];
    const float* bo  = (const float*)d_in[13];

    float* out  = (float*)d_out;
    float* attn = out + (size_t)S * D;

    float *q, *k, *v, *rkt, *rqt, *ctx, *Asc, *Bm, *Cm, *Cd;
    cudaGetSymbolAddress((void**)&q,    g_q);
    cudaGetSymbolAddress((void**)&k,    g_k);
    cudaGetSymbolAddress((void**)&v,    g_v);
    cudaGetSymbolAddress((void**)&rkt,  g_rkt);
    cudaGetSymbolAddress((void**)&rqt,  g_rqt);
    cudaGetSymbolAddress((void**)&ctx,  g_ctx);
    cudaGetSymbolAddress((void**)&Asc,  g_A);
    cudaGetSymbolAddress((void**)&Bm,   g_B);
    cudaGetSymbolAddress((void**)&Cm,   g_C);
    cudaGetSymbolAddress((void**)&Cd,   g_Cd);

    // 1. fused projections (tf32 tensor cores)
    proj_tf32_kernel<<<dim3(4, 8, 5), 256>>>(hs, emb, wq, bq, wk, bk, wv, bv,
                                             wrk, brk, wrq, brq, q, k, v, rkt, rqt);

    // 2. score GEMMs (tf32), 64x64 tiles, pruned
    scores_tf32_kernel<<<dim3(320, H), 128>>>(q, k, rkt, rqt, Asc, Bm, Cm);

    // 3. transpose Sc onto diagonal layout
    cdiag_kernel<<<dim3(72, H), 256>>>(Cm, Cd);

    // 4. fused softmax + ctx (writes attn to d_out and ctx directly)
    smax_ctx_kernel<<<dim3(S / 16, H), 128>>>(Asc, Bm, Cd, v, attn, ctx);

    // 5. out projection (tf32, bias fused)
    out_tf32_kernel<<<dim3(8, 8), 128>>>(ctx, wo, bo, out);
}

// round 13
// speedup vs baseline: 1.5468x; 1.5468x over previous
#include <cuda_runtime.h>

#define S 512
#define D 512
#define H 8
#define HD 64
#define NE 1024

// ---- scratch ----
__device__ float g_q[S * D];
__device__ float g_k[S * D];
__device__ float g_v[S * D];
__device__ float g_rkt[NE * D];
__device__ float g_rqt[NE * D];
__device__ float g_ctx[S * D];
__device__ float g_A[H * S * S];    // q·k     [h,i,j]
__device__ float g_B[H * S * NE];   // q·rkt   [h,i,e]
__device__ float g_C[H * NE * S];   // rqt·k   [h,e,j]
__device__ float g_Cd[H * S * S];   // Sc in diagonal (attn) layout
__device__ float g_part[8 * S * D]; // split-K partials (ctx)

__device__ __forceinline__ unsigned f2tf32(float x) {
    unsigned r;
    asm("cvt.rna.tf32.f32 %0, %1;" : "=r"(r) : "f"(x));
    return r;
}

#define MMA8(c, a, b) \
    asm volatile("mma.sync.aligned.m16n8k8.row.col.f32.tf32.tf32.f32 " \
                 "{%0,%1,%2,%3},{%4,%5,%6,%7},{%8,%9},{%0,%1,%2,%3};" \
                 : "+f"((c)[0]), "+f"((c)[1]), "+f"((c)[2]), "+f"((c)[3]) \
                 : "r"((a)[0]), "r"((a)[1]), "r"((a)[2]), "r"((a)[3]), \
                   "r"((b)[0]), "r"((b)[1]))

// ============================================================
// 64x64 tf32 mma core (128 thr, 4 warps, warp-tile 32x32).
// C[m,n] = sum_k A[m,k] * B[n,k]  (+bias)
// ============================================================
__device__ __forceinline__ void gemm64_tf32_core(
        const float* __restrict__ A, int lda,
        const float* __restrict__ B, int ldb,
        float* __restrict__ Cm, int ldc,
        const float* __restrict__ bias,
        int m0, int n0, int K,
        unsigned (*As)[72], unsigned (*Bs)[72]) {
    const int tid = threadIdx.x;
    const int w = tid >> 5, lane = tid & 31;
    const int g = lane >> 2, tig = lane & 3;
    const int wm = w >> 1, wn = w & 1;
    const int lm = tid >> 1;
    const int lk8 = (tid & 1) * 8;

    float c[2][4][4];
#pragma unroll
    for (int mt = 0; mt < 2; mt++)
#pragma unroll
        for (int nt = 0; nt < 4; nt++)
#pragma unroll
            for (int r = 0; r < 4; r++) c[mt][nt][r] = 0.f;

    for (int k0 = 0; k0 < K; k0 += 16) {
        float4 xa = *(const float4*)(A + (size_t)(m0 + lm) * lda + k0 + lk8);
        float4 ya = *(const float4*)(A + (size_t)(m0 + lm) * lda + k0 + lk8 + 4);
        float4 xb = *(const float4*)(B + (size_t)(n0 + lm) * ldb + k0 + lk8);
        float4 yb = *(const float4*)(B + (size_t)(n0 + lm) * ldb + k0 + lk8 + 4);
        As[lk8 + 0][lm] = f2tf32(xa.x); As[lk8 + 1][lm] = f2tf32(xa.y);
        As[lk8 + 2][lm] = f2tf32(xa.z); As[lk8 + 3][lm] = f2tf32(xa.w);
        As[lk8 + 4][lm] = f2tf32(ya.x); As[lk8 + 5][lm] = f2tf32(ya.y);
        As[lk8 + 6][lm] = f2tf32(ya.z); As[lk8 + 7][lm] = f2tf32(ya.w);
        Bs[lk8 + 0][lm] = f2tf32(xb.x); Bs[lk8 + 1][lm] = f2tf32(xb.y);
        Bs[lk8 + 2][lm] = f2tf32(xb.z); Bs[lk8 + 3][lm] = f2tf32(xb.w);
        Bs[lk8 + 4][lm] = f2tf32(yb.x); Bs[lk8 + 5][lm] = f2tf32(yb.y);
        Bs[lk8 + 6][lm] = f2tf32(yb.z); Bs[lk8 + 7][lm] = f2tf32(yb.w);
        __syncthreads();
#pragma unroll
        for (int ks = 0; ks < 16; ks += 8) {
            const int kb = ks + tig;
            unsigned a[2][4], b[4][2];
#pragma unroll
            for (int mt = 0; mt < 2; mt++) {
                const int ma = wm * 32 + mt * 16 + g;
                a[mt][0] = As[kb][ma];
                a[mt][1] = As[kb][ma + 8];
                a[mt][2] = As[kb + 4][ma];
                a[mt][3] = As[kb + 4][ma + 8];
            }
#pragma unroll
            for (int nt = 0; nt < 4; nt++) {
                const int nb = wn * 32 + nt * 8 + g;
                b[nt][0] = Bs[kb][nb];
                b[nt][1] = Bs[kb + 4][nb];
            }
#pragma unroll
            for (int mt = 0; mt < 2; mt++)
#pragma unroll
                for (int nt = 0; nt < 4; nt++) MMA8(c[mt][nt], a[mt], b[nt]);
        }
        __syncthreads();
    }

#pragma unroll
    for (int mt = 0; mt < 2; mt++) {
        const int r = m0 + wm * 32 + mt * 16 + g;
#pragma unroll
        for (int nt = 0; nt < 4; nt++) {
            const int col = n0 + wn * 32 + nt * 8 + 2 * tig;
            float b0v = 0.f, b1v = 0.f;
            if (bias) { b0v = bias[col]; b1v = bias[col + 1]; }
            *(float2*)(Cm + (size_t)r * ldc + col) =
                make_float2(c[mt][nt][0] + b0v, c[mt][nt][1] + b1v);
            *(float2*)(Cm + (size_t)(r + 8) * ldc + col) =
                make_float2(c[mt][nt][2] + b0v, c[mt][nt][3] + b1v);
        }
    }
}

// ============================================================
// proj (tf32): fused 5-way projection on the 64x64 core.
// grid (8, 16, 5) -> 448 live blocks (~3/SM), 128 thr.
// ============================================================
__global__ __launch_bounds__(128) void proj_tf32_kernel(
        const float* __restrict__ hs, const float* __restrict__ emb,
        const float* __restrict__ wq, const float* __restrict__ bq,
        const float* __restrict__ wk, const float* __restrict__ bk,
        const float* __restrict__ wv, const float* __restrict__ bv,
        const float* __restrict__ wrk, const float* __restrict__ brk,
        const float* __restrict__ wrq, const float* __restrict__ brq,
        float* __restrict__ q, float* __restrict__ k, float* __restrict__ v,
        float* __restrict__ rkt, float* __restrict__ rqt) {
    const float *A, *W, *bias; float* Cm; int M;
    switch (blockIdx.z) {
        case 0: A = hs;  W = wq;  bias = bq;  Cm = q;   M = S;  break;
        case 1: A = hs;  W = wk;  bias = bk;  Cm = k;   M = S;  break;
        case 2: A = hs;  W = wv;  bias = bv;  Cm = v;   M = S;  break;
        case 3: A = emb; W = wrk; bias = brk; Cm = rkt; M = NE; break;
        default:A = emb; W = wrq; bias = brq; Cm = rqt; M = NE; break;
    }
    const int m0 = blockIdx.y * 64, n0 = blockIdx.x * 64;
    if (m0 >= M) return;

    __shared__ unsigned As[16][72];
    __shared__ unsigned Bs[16][72];
    gemm64_tf32_core(A, D, W, D, Cm, D, bias, m0, n0, D, As, Bs);
}

// ============================================================
// scores (tf32): merged A/B/C head GEMMs, 64x64 tiles, pruned.
// ============================================================
__global__ __launch_bounds__(128) void scores_tf32_kernel(
        const float* __restrict__ qf, const float* __restrict__ kf,
        const float* __restrict__ rkt, const float* __restrict__ rqt,
        float* __restrict__ Sa, float* __restrict__ Sb, float* __restrict__ Sc) {
    const int h = blockIdx.y;
    int bi = blockIdx.x;
    const float *A, *B; float* Cm; int m0, n0, ldc;

    if (bi < 64) {
        m0 = (bi >> 3) * 64; n0 = (bi & 7) * 64;
        A = qf; B = kf; Cm = Sa + (size_t)h * S * S; ldc = S;
    } else if (bi < 192) {
        bi -= 64;
        m0 = (bi >> 4) * 64; n0 = (bi & 15) * 64;
        const int sum = m0 + n0;
        if (sum + 126 < 512 || sum > 1023) return;
        A = qf; B = rkt; Cm = Sb + (size_t)h * S * NE; ldc = NE;
    } else {
        bi -= 192;
        m0 = (bi >> 3) * 64; n0 = (bi & 7) * 64;
        const int d = m0 - n0;
        if (d < 0 || d > 512) return;
        A = rqt; B = kf; Cm = Sc + (size_t)h * NE * S; ldc = S;
    }
    A += h * HD; B += h * HD;

    __shared__ unsigned As[16][72];
    __shared__ unsigned Bs[16][72];
    gemm64_tf32_core(A, D, B, D, Cm, ldc, nullptr, m0, n0, HD, As, Bs);
}

// ============================================================
// cdiag: smem-transpose Sc live tiles onto diagonal layout
// Cd[h,i,j] = Sc[h, j-i+512, j].
// ============================================================
__global__ __launch_bounds__(256) void cdiag_kernel(const float* __restrict__ Cm,
                                                    float* __restrict__ Cd) {
    const int h = blockIdx.y;
    const int tj = blockIdx.x / 9, r = blockIdx.x % 9;
    const int te = tj + r;
    const int e0 = te * 64, j0 = tj * 64;
    const int ib = 512 + j0 - e0;

    __shared__ float t[64][65];
    const int tid = threadIdx.x;
    const int lr = tid >> 4;
    const int lc4 = (tid & 15) * 4;
#pragma unroll
    for (int rr = 0; rr < 64; rr += 16) {
        float4 v = *(const float4*)(Cm + ((size_t)h * NE + e0 + rr + lr) * S + j0 + lc4);
        t[rr + lr][lc4 + 0] = v.x; t[rr + lr][lc4 + 1] = v.y;
        t[rr + lr][lc4 + 2] = v.z; t[rr + lr][lc4 + 3] = v.w;
    }
    __syncthreads();

    const int sub = tid >> 6;
    const int lj = tid & 63;
#pragma unroll 4
    for (int rr = 0; rr < 128; rr += 4) {
        const int dd = rr + sub - 63;
        const int i = ib + dd;
        if (i >= 0 && i < S && lj >= dd && lj <= 63 + dd) {
            const int le = lj - dd;
            Cd[((size_t)h * S + i) * S + j0 + lj] = t[le][lj];
        }
    }
}

// ============================================================
// out-proj (tf32): out = ctx @ wo^T + bo, 64x64 tiles, K=512.
// ============================================================
__global__ __launch_bounds__(128) void out_tf32_kernel(
        const float* __restrict__ ctx, const float* __restrict__ wo,
        const float* __restrict__ bo, float* __restrict__ out) {
    __shared__ unsigned As[16][72];
    __shared__ unsigned Bs[16][72];
    gemm64_tf32_core(ctx, D, wo, D, out, D, bo,
                     blockIdx.y * 64, blockIdx.x * 64, D, As, Bs);
}

// ============================================================
// warp-per-row softmax; all three score terms contiguous.
// ============================================================
__global__ __launch_bounds__(128) void softmax_warp_kernel(
        const float* __restrict__ Asc, const float* __restrict__ Bm,
        const float* __restrict__ Cd, float* __restrict__ attn) {
    const int h = blockIdx.y;
    const int warp = threadIdx.x >> 5, lane = threadIdx.x & 31;
    const int i = blockIdx.x * 4 + warp;

    const float* aRow = Asc + ((size_t)h * S + i) * S;
    const float* bRow = Bm + ((size_t)h * S + i) * NE + (512 - i);
    const float* cRow = Cd + ((size_t)h * S + i) * S;

    float sc[16];
#pragma unroll
    for (int t = 0; t < 16; t++) {
        const int j = t * 32 + lane;
        sc[t] = (aRow[j] + bRow[j] + cRow[j]) * 0.125f;
    }

    float mx = sc[0];
#pragma unroll
    for (int t = 1; t < 16; t++) mx = fmaxf(mx, sc[t]);
#pragma unroll
    for (int o = 16; o; o >>= 1) mx = fmaxf(mx, __shfl_xor_sync(0xffffffffu, mx, o));

    float sum = 0.f;
#pragma unroll
    for (int t = 0; t < 16; t++) {
        sc[t] = __expf(sc[t] - mx);
        sum += sc[t];
    }
#pragma unroll
    for (int o = 16; o; o >>= 1) sum += __shfl_xor_sync(0xffffffffu, sum, o);
    const float inv = 1.f / sum;

    float* oRow = attn + ((size_t)h * S + i) * S;
#pragma unroll
    for (int t = 0; t < 16; t++) oRow[t * 32 + lane] = sc[t] * inv;
}

// ============================================================
// ctx split-K8 (fp32 FFMA): 64x64 tile, float4 fragment loads.
// ============================================================
__global__ __launch_bounds__(256) void ctx_part_kernel(
        const float* __restrict__ attn, const float* __restrict__ vf,
        float* __restrict__ part) {
    const int mt = blockIdx.x, ks = blockIdx.y, h = blockIdx.z;
    const int m0 = mt * 64;
    const float* A = attn + (size_t)h * S * S;
    const float* B = vf + h * HD;

    __shared__ float As[16][68];
    __shared__ float Bs[16][68];

    const int tid = threadIdx.x;
    const int tx = tid & 15, ty = tid >> 4;
    const int lm = tid >> 2, lk = (tid & 3) * 4;
    const int rk = tid >> 4, nc4 = (tid & 15) * 4;

    float acc[4][4];
#pragma unroll
    for (int i = 0; i < 4; i++)
#pragma unroll
        for (int j = 0; j < 4; j++) acc[i][j] = 0.f;

    const int kbeg = ks * 64;
#pragma unroll 1
    for (int k0 = kbeg; k0 < kbeg + 64; k0 += 16) {
        float4 av = *(const float4*)(A + (size_t)(m0 + lm) * S + k0 + lk);
        As[lk + 0][lm] = av.x; As[lk + 1][lm] = av.y;
        As[lk + 2][lm] = av.z; As[lk + 3][lm] = av.w;
        float4 bv = *(const float4*)(B + (size_t)(k0 + rk) * D + nc4);
        *(float4*)&Bs[rk][nc4] = bv;
        __syncthreads();
#pragma unroll
        for (int kk = 0; kk < 16; kk++) {
            float4 a4 = *(const float4*)&As[kk][ty * 4];
            float4 b4 = *(const float4*)&Bs[kk][tx * 4];
            float a[4] = {a4.x, a4.y, a4.z, a4.w};
            float b[4] = {b4.x, b4.y, b4.z, b4.w};
#pragma unroll
            for (int i = 0; i < 4; i++)
#pragma unroll
                for (int j = 0; j < 4; j++) acc[i][j] += a[i] * b[j];
        }
        __syncthreads();
    }

    float* Cm = part + (size_t)ks * S * D + h * HD;
#pragma unroll
    for (int i = 0; i < 4; i++) {
        const int m = m0 + ty * 4 + i;
        *(float4*)(Cm + (size_t)m * D + tx * 4) =
            make_float4(acc[i][0], acc[i][1], acc[i][2], acc[i][3]);
    }
}

__global__ void reduce8_kernel(const float* __restrict__ part, float* __restrict__ dst) {
    const int idx = (blockIdx.x * 256 + threadIdx.x) * 4;
    float4 r = *(const float4*)(part + idx);
#pragma unroll
    for (int p = 1; p < 8; p++) {
        float4 x = *(const float4*)(part + (size_t)p * S * D + idx);
        r.x += x.x; r.y += x.y; r.z += x.z; r.w += x.w;
    }
    *(float4*)(dst + idx) = r;
}

extern "C" void kernel_launch(void* const* d_in, const int* in_sizes, int n_in,
                              void* d_out, int out_size) {
    const float* hs  = (const float*)d_in[0];
    const float* emb = (const float*)d_in[1];
    const float* wq  = (const float*)d_in[2];
    const float* bq  = (const float*)d_in[3];
    const float* wk  = (const float*)d_in[4];
    const float* bk  = (const float*)d_in[5];
    const float* wv  = (const float*)d_in[6];
    const float* bv  = (const float*)d_in[7];
    const float* wrk = (const float*)d_in[8];
    const float* brk = (const float*)d_in[9];
    const float* wrq = (const float*)d_in[10];
    const float* brq = (const float*)d_in[11];
    const float* wo  = (const float*)d_in[12];
    const float* bo  = (const float*)d_in[13];

    float* out  = (float*)d_out;
    float* attn = out + (size_t)S * D;

    float *q, *k, *v, *rkt, *rqt, *ctx, *Asc, *Bm, *Cm, *Cd, *part;
    cudaGetSymbolAddress((void**)&q,    g_q);
    cudaGetSymbolAddress((void**)&k,    g_k);
    cudaGetSymbolAddress((void**)&v,    g_v);
    cudaGetSymbolAddress((void**)&rkt,  g_rkt);
    cudaGetSymbolAddress((void**)&rqt,  g_rqt);
    cudaGetSymbolAddress((void**)&ctx,  g_ctx);
    cudaGetSymbolAddress((void**)&Asc,  g_A);
    cudaGetSymbolAddress((void**)&Bm,   g_B);
    cudaGetSymbolAddress((void**)&Cm,   g_C);
    cudaGetSymbolAddress((void**)&Cd,   g_Cd);
    cudaGetSymbolAddress((void**)&part, g_part);

    // 1. fused projections (tf32, 64x64 tiles, 448 live blocks)
    proj_tf32_kernel<<<dim3(8, 16, 5), 128>>>(hs, emb, wq, bq, wk, bk, wv, bv,
                                              wrk, brk, wrq, brq, q, k, v, rkt, rqt);

    // 2. score GEMMs (tf32), 64x64 tiles, pruned
    scores_tf32_kernel<<<dim3(320, H), 128>>>(q, k, rkt, rqt, Asc, Bm, Cm);

    // 3. transpose Sc onto diagonal layout
    cdiag_kernel<<<dim3(72, H), 256>>>(Cm, Cd);

    // 4. warp-per-row softmax -> attn (in d_out)
    softmax_warp_kernel<<<dim3(S / 4, H), 128>>>(Asc, Bm, Cd, attn);

    // 5. ctx split-K8 (512 blocks, float4 fragments) + reduce
    ctx_part_kernel<<<dim3(8, 8, H), 256>>>(attn, v, part);
    reduce8_kernel<<<256, 256>>>(part, ctx);

    // 6. out projection (tf32, bias fused)
    out_tf32_kernel<<<dim3(8, 8), 128>>>(ctx, wo, bo, out);
}

// round 14
// speedup vs baseline: 1.7533x; 1.1335x over previous
#include <cuda_runtime.h>

#define S 512
#define D 512
#define H 8
#define HD 64
#define NE 1024

// ---- scratch ----
__device__ float g_q[S * D];
__device__ float g_k[S * D];
__device__ float g_v[S * D];
__device__ float g_rkt[NE * D];
__device__ float g_rqt[NE * D];
__device__ float g_ctx[S * D];
__device__ float g_A[H * S * S];    // q·k     [h,i,j]
__device__ float g_B[H * S * NE];   // q·rkt   [h,i,e]
__device__ float g_Cd[H * S * S];   // rqt·k in diagonal (attn) layout
__device__ float g_part[8 * S * D]; // split-K partials (ctx, then out)

__device__ __forceinline__ unsigned f2tf32(float x) {
    unsigned r;
    asm("cvt.rna.tf32.f32 %0, %1;" : "=r"(r) : "f"(x));
    return r;
}

#define MMA8(c, a, b) \
    asm volatile("mma.sync.aligned.m16n8k8.row.col.f32.tf32.tf32.f32 " \
                 "{%0,%1,%2,%3},{%4,%5,%6,%7},{%8,%9},{%0,%1,%2,%3};" \
                 : "+f"((c)[0]), "+f"((c)[1]), "+f"((c)[2]), "+f"((c)[3]) \
                 : "r"((a)[0]), "r"((a)[1]), "r"((a)[2]), "r"((a)[3]), \
                   "r"((b)[0]), "r"((b)[1]))

// ============================================================
// proj (tf32 mma): fused 5-way projection. 128x128 tile, 256 thr,
// global double-buffer (R10 version — measured best).
// ============================================================
__global__ __launch_bounds__(256) void proj_tf32_kernel(
        const float* __restrict__ hs, const float* __restrict__ emb,
        const float* __restrict__ wq, const float* __restrict__ bq,
        const float* __restrict__ wk, const float* __restrict__ bk,
        const float* __restrict__ wv, const float* __restrict__ bv,
        const float* __restrict__ wrk, const float* __restrict__ brk,
        const float* __restrict__ wrq, const float* __restrict__ brq,
        float* __restrict__ q, float* __restrict__ k, float* __restrict__ v,
        float* __restrict__ rkt, float* __restrict__ rqt) {
    const float *A, *W, *bias; float* Cm; int M;
    switch (blockIdx.z) {
        case 0: A = hs;  W = wq;  bias = bq;  Cm = q;   M = S;  break;
        case 1: A = hs;  W = wk;  bias = bk;  Cm = k;   M = S;  break;
        case 2: A = hs;  W = wv;  bias = bv;  Cm = v;   M = S;  break;
        case 3: A = emb; W = wrk; bias = brk; Cm = rkt; M = NE; break;
        default:A = emb; W = wrq; bias = brq; Cm = rqt; M = NE; break;
    }
    const int m0 = blockIdx.y * 128, n0 = blockIdx.x * 128;
    if (m0 >= M) return;

    __shared__ unsigned As[2][16][136];
    __shared__ unsigned Bs[2][16][136];

    const int tid = threadIdx.x;
    const int r0 = tid >> 2;
    const int c4 = (tid & 3) * 4;
    const int w = tid >> 5, lane = tid & 31;
    const int g = lane >> 2, tig = lane & 3;
    const int wm = w >> 1, wn = w & 1;

    const float* Ar0 = A + (size_t)(m0 + r0) * D + c4;
    const float* Ar1 = A + (size_t)(m0 + 64 + r0) * D + c4;
    const float* Wr0 = W + (size_t)(n0 + r0) * D + c4;
    const float* Wr1 = W + (size_t)(n0 + 64 + r0) * D + c4;

    float4 pa0, pa1, pb0, pb1;

#define PGLOAD(K0) do { \
        pa0 = *(const float4*)(Ar0 + (K0)); \
        pa1 = *(const float4*)(Ar1 + (K0)); \
        pb0 = *(const float4*)(Wr0 + (K0)); \
        pb1 = *(const float4*)(Wr1 + (K0)); } while (0)

#define PGSTORE(BUF) do { \
        As[BUF][c4 + 0][r0] = f2tf32(pa0.x); As[BUF][c4 + 1][r0] = f2tf32(pa0.y); \
        As[BUF][c4 + 2][r0] = f2tf32(pa0.z); As[BUF][c4 + 3][r0] = f2tf32(pa0.w); \
        As[BUF][c4 + 0][64 + r0] = f2tf32(pa1.x); As[BUF][c4 + 1][64 + r0] = f2tf32(pa1.y); \
        As[BUF][c4 + 2][64 + r0] = f2tf32(pa1.z); As[BUF][c4 + 3][64 + r0] = f2tf32(pa1.w); \
        Bs[BUF][c4 + 0][r0] = f2tf32(pb0.x); Bs[BUF][c4 + 1][r0] = f2tf32(pb0.y); \
        Bs[BUF][c4 + 2][r0] = f2tf32(pb0.z); Bs[BUF][c4 + 3][r0] = f2tf32(pb0.w); \
        Bs[BUF][c4 + 0][64 + r0] = f2tf32(pb1.x); Bs[BUF][c4 + 1][64 + r0] = f2tf32(pb1.y); \
        Bs[BUF][c4 + 2][64 + r0] = f2tf32(pb1.z); Bs[BUF][c4 + 3][64 + r0] = f2tf32(pb1.w); } while (0)

    float c[2][8][4];
#pragma unroll
    for (int mt = 0; mt < 2; mt++)
#pragma unroll
        for (int nt = 0; nt < 8; nt++)
#pragma unroll
            for (int r = 0; r < 4; r++) c[mt][nt][r] = 0.f;

    PGLOAD(0);
    PGSTORE(0);
    __syncthreads();

    int buf = 0;
    for (int k0 = 0; k0 < D; k0 += 16) {
        const bool more = (k0 + 16 < D);
        if (more) PGLOAD(k0 + 16);
#pragma unroll
        for (int ks = 0; ks < 16; ks += 8) {
            const int kb = ks + tig;
            unsigned a[2][4], b[8][2];
#pragma unroll
            for (int mt = 0; mt < 2; mt++) {
                const int ma = wm * 32 + mt * 16 + g;
                a[mt][0] = As[buf][kb][ma];
                a[mt][1] = As[buf][kb][ma + 8];
                a[mt][2] = As[buf][kb + 4][ma];
                a[mt][3] = As[buf][kb + 4][ma + 8];
            }
#pragma unroll
            for (int nt = 0; nt < 8; nt++) {
                const int nb = wn * 64 + nt * 8 + g;
                b[nt][0] = Bs[buf][kb][nb];
                b[nt][1] = Bs[buf][kb + 4][nb];
            }
#pragma unroll
            for (int mt = 0; mt < 2; mt++)
#pragma unroll
                for (int nt = 0; nt < 8; nt++) MMA8(c[mt][nt], a[mt], b[nt]);
        }
        if (more) {
            buf ^= 1;
            PGSTORE(buf);
            __syncthreads();
        }
    }

#pragma unroll
    for (int mt = 0; mt < 2; mt++) {
        const int r = m0 + wm * 32 + mt * 16 + g;
#pragma unroll
        for (int nt = 0; nt < 8; nt++) {
            const int col = n0 + wn * 64 + nt * 8 + 2 * tig;
            const float b0v = bias[col], b1v = bias[col + 1];
            *(float2*)(Cm + (size_t)r * D + col) =
                make_float2(c[mt][nt][0] + b0v, c[mt][nt][1] + b1v);
            *(float2*)(Cm + (size_t)(r + 8) * D + col) =
                make_float2(c[mt][nt][2] + b0v, c[mt][nt][3] + b1v);
        }
    }
#undef PGLOAD
#undef PGSTORE
}

// ============================================================
// 64x64 tf32 mma core. If stage != nullptr, the tile is written
// to smem staging (local coords) instead of global.
// ============================================================
__device__ __forceinline__ void gemm64_tf32_core(
        const float* __restrict__ A, int lda,
        const float* __restrict__ B, int ldb,
        float* __restrict__ Cm, int ldc,
        const float* __restrict__ bias,
        int m0, int n0, int K,
        unsigned (*As)[72], unsigned (*Bs)[72],
        float (*stage)[68]) {
    const int tid = threadIdx.x;
    const int w = tid >> 5, lane = tid & 31;
    const int g = lane >> 2, tig = lane & 3;
    const int wm = w >> 1, wn = w & 1;
    const int lm = tid >> 1;
    const int lk8 = (tid & 1) * 8;

    float c[2][4][4];
#pragma unroll
    for (int mt = 0; mt < 2; mt++)
#pragma unroll
        for (int nt = 0; nt < 4; nt++)
#pragma unroll
            for (int r = 0; r < 4; r++) c[mt][nt][r] = 0.f;

    for (int k0 = 0; k0 < K; k0 += 16) {
        float4 xa = *(const float4*)(A + (size_t)(m0 + lm) * lda + k0 + lk8);
        float4 ya = *(const float4*)(A + (size_t)(m0 + lm) * lda + k0 + lk8 + 4);
        float4 xb = *(const float4*)(B + (size_t)(n0 + lm) * ldb + k0 + lk8);
        float4 yb = *(const float4*)(B + (size_t)(n0 + lm) * ldb + k0 + lk8 + 4);
        As[lk8 + 0][lm] = f2tf32(xa.x); As[lk8 + 1][lm] = f2tf32(xa.y);
        As[lk8 + 2][lm] = f2tf32(xa.z); As[lk8 + 3][lm] = f2tf32(xa.w);
        As[lk8 + 4][lm] = f2tf32(ya.x); As[lk8 + 5][lm] = f2tf32(ya.y);
        As[lk8 + 6][lm] = f2tf32(ya.z); As[lk8 + 7][lm] = f2tf32(ya.w);
        Bs[lk8 + 0][lm] = f2tf32(xb.x); Bs[lk8 + 1][lm] = f2tf32(xb.y);
        Bs[lk8 + 2][lm] = f2tf32(xb.z); Bs[lk8 + 3][lm] = f2tf32(xb.w);
        Bs[lk8 + 4][lm] = f2tf32(yb.x); Bs[lk8 + 5][lm] = f2tf32(yb.y);
        Bs[lk8 + 6][lm] = f2tf32(yb.z); Bs[lk8 + 7][lm] = f2tf32(yb.w);
        __syncthreads();
#pragma unroll
        for (int ks = 0; ks < 16; ks += 8) {
            const int kb = ks + tig;
            unsigned a[2][4], b[4][2];
#pragma unroll
            for (int mt = 0; mt < 2; mt++) {
                const int ma = wm * 32 + mt * 16 + g;
                a[mt][0] = As[kb][ma];
                a[mt][1] = As[kb][ma + 8];
                a[mt][2] = As[kb + 4][ma];
                a[mt][3] = As[kb + 4][ma + 8];
            }
#pragma unroll
            for (int nt = 0; nt < 4; nt++) {
                const int nb = wn * 32 + nt * 8 + g;
                b[nt][0] = Bs[kb][nb];
                b[nt][1] = Bs[kb + 4][nb];
            }
#pragma unroll
            for (int mt = 0; mt < 2; mt++)
#pragma unroll
                for (int nt = 0; nt < 4; nt++) MMA8(c[mt][nt], a[mt], b[nt]);
        }
        __syncthreads();
    }

    if (stage) {
#pragma unroll
        for (int mt = 0; mt < 2; mt++) {
            const int lr = wm * 32 + mt * 16 + g;
#pragma unroll
            for (int nt = 0; nt < 4; nt++) {
                const int col = wn * 32 + nt * 8 + 2 * tig;
                stage[lr][col + 0] = c[mt][nt][0];
                stage[lr][col + 1] = c[mt][nt][1];
                stage[lr + 8][col + 0] = c[mt][nt][2];
                stage[lr + 8][col + 1] = c[mt][nt][3];
            }
        }
        return;
    }

#pragma unroll
    for (int mt = 0; mt < 2; mt++) {
        const int r = m0 + wm * 32 + mt * 16 + g;
#pragma unroll
        for (int nt = 0; nt < 4; nt++) {
            const int col = n0 + wn * 32 + nt * 8 + 2 * tig;
            float b0v = 0.f, b1v = 0.f;
            if (bias) { b0v = bias[col]; b1v = bias[col + 1]; }
            *(float2*)(Cm + (size_t)r * ldc + col) =
                make_float2(c[mt][nt][0] + b0v, c[mt][nt][1] + b1v);
            *(float2*)(Cm + (size_t)(r + 8) * ldc + col) =
                make_float2(c[mt][nt][2] + b0v, c[mt][nt][3] + b1v);
        }
    }
}

// ============================================================
// scores (tf32): merged A/B/C head GEMMs, 64x64 tiles, pruned.
// Sc branch writes DIRECTLY to diagonal layout Cd (cdiag folded
// in): stage tile in smem, scatter per-diagonal coalesced rows.
// ============================================================
__global__ __launch_bounds__(128) void scores_tf32_kernel(
        const float* __restrict__ qf, const float* __restrict__ kf,
        const float* __restrict__ rkt, const float* __restrict__ rqt,
        float* __restrict__ Sa, float* __restrict__ Sb, float* __restrict__ Cd) {
    const int h = blockIdx.y;
    int bi = blockIdx.x;
    const float *A, *B; float* Cm = nullptr; int m0, n0, ldc = 0;
    bool diag = false;

    if (bi < 64) {
        m0 = (bi >> 3) * 64; n0 = (bi & 7) * 64;
        A = qf; B = kf; Cm = Sa + (size_t)h * S * S; ldc = S;
    } else if (bi < 192) {
        bi -= 64;
        m0 = (bi >> 4) * 64; n0 = (bi & 15) * 64;
        const int sum = m0 + n0;
        if (sum + 126 < 512 || sum > 1023) return;
        A = qf; B = rkt; Cm = Sb + (size_t)h * S * NE; ldc = NE;
    } else {
        bi -= 192;
        m0 = (bi >> 3) * 64; n0 = (bi & 7) * 64;   // rows e, cols j
        const int d = m0 - n0;
        if (d < 0 || d > 512) return;
        A = rqt; B = kf; diag = true;
    }
    A += h * HD; B += h * HD;

    __shared__ unsigned As[16][72];
    __shared__ unsigned Bs[16][72];
    __shared__ float st[64][68];

    gemm64_tf32_core(A, D, B, D, Cm, ldc, nullptr, m0, n0, HD, As, Bs,
                     diag ? st : nullptr);

    if (diag) {
        __syncthreads();
        // tile rows are e (m0 base), cols are j (n0 base).
        // i = j - e + 512 ; diagonal dd = lj - le ; i = ib + dd.
        const int ib = 512 + n0 - m0;
        const int tid = threadIdx.x;
        const int sub = tid >> 6;       // 2 diagonals in parallel
        const int lj = tid & 63;
        float* CdH = Cd + (size_t)h * S * S;
#pragma unroll 8
        for (int rr = 0; rr < 128; rr += 2) {
            const int dd = rr + sub - 63;
            const int i = ib + dd;
            if (i >= 0 && i < S && lj >= dd && lj <= 63 + dd)
                CdH[(size_t)i * S + n0 + lj] = st[lj - dd][lj];
        }
    }
}

// ============================================================
// out-proj split-K2 (tf32): part[ks] = ctx[:,ks*256:+256] @ wo^T
// ============================================================
__global__ __launch_bounds__(128) void out_part_tf32_kernel(
        const float* __restrict__ ctx, const float* __restrict__ wo,
        float* __restrict__ part) {
    const int ks = blockIdx.z;
    __shared__ unsigned As[16][72];
    __shared__ unsigned Bs[16][72];
    gemm64_tf32_core(ctx + ks * 256, D, wo + ks * 256, D,
                     part + (size_t)ks * S * D, D, nullptr,
                     blockIdx.y * 64, blockIdx.x * 64, 256, As, Bs, nullptr);
}

__global__ void reduce2_bias_kernel(const float* __restrict__ part,
                                    const float* __restrict__ bias,
                                    float* __restrict__ dst) {
    const int idx = (blockIdx.x * 256 + threadIdx.x) * 4;
    float4 a = *(const float4*)(part + idx);
    float4 b = *(const float4*)(part + S * D + idx);
    float4 bi = *(const float4*)(bias + (idx & (D - 1)));
    *(float4*)(dst + idx) = make_float4(a.x + b.x + bi.x, a.y + b.y + bi.y,
                                        a.z + b.z + bi.z, a.w + b.w + bi.w);
}

// ============================================================
// warp-per-row softmax; all three score terms contiguous.
// ============================================================
__global__ __launch_bounds__(128) void softmax_warp_kernel(
        const float* __restrict__ Asc, const float* __restrict__ Bm,
        const float* __restrict__ Cd, float* __restrict__ attn) {
    const int h = blockIdx.y;
    const int warp = threadIdx.x >> 5, lane = threadIdx.x & 31;
    const int i = blockIdx.x * 4 + warp;

    const float* aRow = Asc + ((size_t)h * S + i) * S;
    const float* bRow = Bm + ((size_t)h * S + i) * NE + (512 - i);
    const float* cRow = Cd + ((size_t)h * S + i) * S;

    float sc[16];
#pragma unroll
    for (int t = 0; t < 16; t++) {
        const int j = t * 32 + lane;
        sc[t] = (aRow[j] + bRow[j] + cRow[j]) * 0.125f;
    }

    float mx = sc[0];
#pragma unroll
    for (int t = 1; t < 16; t++) mx = fmaxf(mx, sc[t]);
#pragma unroll
    for (int o = 16; o; o >>= 1) mx = fmaxf(mx, __shfl_xor_sync(0xffffffffu, mx, o));

    float sum = 0.f;
#pragma unroll
    for (int t = 0; t < 16; t++) {
        sc[t] = __expf(sc[t] - mx);
        sum += sc[t];
    }
#pragma unroll
    for (int o = 16; o; o >>= 1) sum += __shfl_xor_sync(0xffffffffu, sum, o);
    const float inv = 1.f / sum;

    float* oRow = attn + ((size_t)h * S + i) * S;
#pragma unroll
    for (int t = 0; t < 16; t++) oRow[t * 32 + lane] = sc[t] * inv;
}

// ============================================================
// ctx split-K8 (fp32 FFMA): 64x64 tile, float4 fragment loads.
// ============================================================
__global__ __launch_bounds__(256) void ctx_part_kernel(
        const float* __restrict__ attn, const float* __restrict__ vf,
        float* __restrict__ part) {
    const int mt = blockIdx.x, ks = blockIdx.y, h = blockIdx.z;
    const int m0 = mt * 64;
    const float* A = attn + (size_t)h * S * S;
    const float* B = vf + h * HD;

    __shared__ float As[16][68];
    __shared__ float Bs[16][68];

    const int tid = threadIdx.x;
    const int tx = tid & 15, ty = tid >> 4;
    const int lm = tid >> 2, lk = (tid & 3) * 4;
    const int rk = tid >> 4, nc4 = (tid & 15) * 4;

    float acc[4][4];
#pragma unroll
    for (int i = 0; i < 4; i++)
#pragma unroll
        for (int j = 0; j < 4; j++) acc[i][j] = 0.f;

    const int kbeg = ks * 64;
#pragma unroll 1
    for (int k0 = kbeg; k0 < kbeg + 64; k0 += 16) {
        float4 av = *(const float4*)(A + (size_t)(m0 + lm) * S + k0 + lk);
        As[lk + 0][lm] = av.x; As[lk + 1][lm] = av.y;
        As[lk + 2][lm] = av.z; As[lk + 3][lm] = av.w;
        float4 bv = *(const float4*)(B + (size_t)(k0 + rk) * D + nc4);
        *(float4*)&Bs[rk][nc4] = bv;
        __syncthreads();
#pragma unroll
        for (int kk = 0; kk < 16; kk++) {
            float4 a4 = *(const float4*)&As[kk][ty * 4];
            float4 b4 = *(const float4*)&Bs[kk][tx * 4];
            float a[4] = {a4.x, a4.y, a4.z, a4.w};
            float b[4] = {b4.x, b4.y, b4.z, b4.w};
#pragma unroll
            for (int i = 0; i < 4; i++)
#pragma unroll
                for (int j = 0; j < 4; j++) acc[i][j] += a[i] * b[j];
        }
        __syncthreads();
    }

    float* Cm = part + (size_t)ks * S * D + h * HD;
#pragma unroll
    for (int i = 0; i < 4; i++) {
        const int m = m0 + ty * 4 + i;
        *(float4*)(Cm + (size_t)m * D + tx * 4) =
            make_float4(acc[i][0], acc[i][1], acc[i][2], acc[i][3]);
    }
}

__global__ void reduce8_kernel(const float* __restrict__ part, float* __restrict__ dst) {
    const int idx = (blockIdx.x * 256 + threadIdx.x) * 4;
    float4 r = *(const float4*)(part + idx);
#pragma unroll
    for (int p = 1; p < 8; p++) {
        float4 x = *(const float4*)(part + (size_t)p * S * D + idx);
        r.x += x.x; r.y += x.y; r.z += x.z; r.w += x.w;
    }
    *(float4*)(dst + idx) = r;
}

extern "C" void kernel_launch(void* const* d_in, const int* in_sizes, int n_in,
                              void* d_out, int out_size) {
    const float* hs  = (const float*)d_in[0];
    const float* emb = (const float*)d_in[1];
    const float* wq  = (const float*)d_in[2];
    const float* bq  = (const float*)d_in[3];
    const float* wk  = (const float*)d_in[4];
    const float* bk  = (const float*)d_in[5];
    const float* wv  = (const float*)d_in[6];
    const float* bv  = (const float*)d_in[7];
    const float* wrk = (const float*)d_in[8];
    const float* brk = (const float*)d_in[9];
    const float* wrq = (const float*)d_in[10];
    const float* brq = (const float*)d_in[11];
    const float* wo  = (const float*)d_in[12];
    const float* bo  = (const float*)d_in[13];

    float* out  = (float*)d_out;
    float* attn = out + (size_t)S * D;

    float *q, *k, *v, *rkt, *rqt, *ctx, *Asc, *Bm, *Cd, *part;
    cudaGetSymbolAddress((void**)&q,    g_q);
    cudaGetSymbolAddress((void**)&k,    g_k);
    cudaGetSymbolAddress((void**)&v,    g_v);
    cudaGetSymbolAddress((void**)&rkt,  g_rkt);
    cudaGetSymbolAddress((void**)&rqt,  g_rqt);
    cudaGetSymbolAddress((void**)&ctx,  g_ctx);
    cudaGetSymbolAddress((void**)&Asc,  g_A);
    cudaGetSymbolAddress((void**)&Bm,   g_B);
    cudaGetSymbolAddress((void**)&Cd,   g_Cd);
    cudaGetSymbolAddress((void**)&part, g_part);

    // 1. fused projections (tf32, 128x128, R10 config)
    proj_tf32_kernel<<<dim3(4, 8, 5), 256>>>(hs, emb, wq, bq, wk, bk, wv, bv,
                                             wrk, brk, wrq, brq, q, k, v, rkt, rqt);

    // 2. score GEMMs (tf32); Sc written directly in diagonal layout
    scores_tf32_kernel<<<dim3(320, H), 128>>>(q, k, rkt, rqt, Asc, Bm, Cd);

    // 3. warp-per-row softmax -> attn (in d_out), all reads contiguous
    softmax_warp_kernel<<<dim3(S / 4, H), 128>>>(Asc, Bm, Cd, attn);

    // 4. ctx split-K8 (512 blocks) + reduce
    ctx_part_kernel<<<dim3(8, 8, H), 256>>>(attn, v, part);
    reduce8_kernel<<<256, 256>>>(part, ctx);

    // 5. out projection split-K2 (128 blocks) + bias reduce
    out_part_tf32_kernel<<<dim3(8, 8, 2), 128>>>(ctx, wo, part);
    reduce2_bias_kernel<<<256, 256>>>(part, bo, out);
}

// round 17
// speedup vs baseline: 1.7582x; 1.0027x over previous
#include <cuda_runtime.h>

#define S 512
#define D 512
#define H 8
#define HD 64
#define NE 1024

// ---- scratch ----
__device__ float g_q[S * D];
__device__ float g_k[S * D];
__device__ float g_v[S * D];
__device__ float g_rkt[NE * D];
__device__ float g_rqt[NE * D];
__device__ float g_ctx[S * D];
__device__ float g_A[H * S * S];    // q·k     [h,i,j]
__device__ float g_B[H * S * NE];   // q·rkt   [h,i,e]
__device__ float g_Cd[H * S * S];   // rqt·k in diagonal (attn) layout
__device__ float g_part[8 * S * D]; // split-K partials (ctx, then out)

__device__ __forceinline__ unsigned f2tf32(float x) {
    unsigned r;
    asm("cvt.rna.tf32.f32 %0, %1;" : "=r"(r) : "f"(x));
    return r;
}

#define MMA8(c, a, b) \
    asm volatile("mma.sync.aligned.m16n8k8.row.col.f32.tf32.tf32.f32 " \
                 "{%0,%1,%2,%3},{%4,%5,%6,%7},{%8,%9},{%0,%1,%2,%3};" \
                 : "+f"((c)[0]), "+f"((c)[1]), "+f"((c)[2]), "+f"((c)[3]) \
                 : "r"((a)[0]), "r"((a)[1]), "r"((a)[2]), "r"((a)[3]), \
                   "r"((b)[0]), "r"((b)[1]))

// ============================================================
// proj (tf32 mma): fused 5-way projection. 128x64 tile, 256 thr,
// K=512 with global double-buffer. 224 live blocks (~1.5/SM).
// ============================================================
__global__ __launch_bounds__(256) void proj_tf32_kernel(
        const float* __restrict__ hs, const float* __restrict__ emb,
        const float* __restrict__ wq, const float* __restrict__ bq,
        const float* __restrict__ wk, const float* __restrict__ bk,
        const float* __restrict__ wv, const float* __restrict__ bv,
        const float* __restrict__ wrk, const float* __restrict__ brk,
        const float* __restrict__ wrq, const float* __restrict__ brq,
        float* __restrict__ q, float* __restrict__ k, float* __restrict__ v,
        float* __restrict__ rkt, float* __restrict__ rqt) {
    const float *A, *W, *bias; float* Cm; int M;
    switch (blockIdx.z) {
        case 0: A = hs;  W = wq;  bias = bq;  Cm = q;   M = S;  break;
        case 1: A = hs;  W = wk;  bias = bk;  Cm = k;   M = S;  break;
        case 2: A = hs;  W = wv;  bias = bv;  Cm = v;   M = S;  break;
        case 3: A = emb; W = wrk; bias = brk; Cm = rkt; M = NE; break;
        default:A = emb; W = wrq; bias = brq; Cm = rqt; M = NE; break;
    }
    const int m0 = blockIdx.y * 128, n0 = blockIdx.x * 64;
    if (m0 >= M) return;

    __shared__ unsigned As[2][16][136];
    __shared__ unsigned Bs[2][16][72];

    const int tid = threadIdx.x;
    const int r0 = tid >> 2;
    const int c4 = (tid & 3) * 4;
    const int w = tid >> 5, lane = tid & 31;
    const int g = lane >> 2, tig = lane & 3;
    const int wm = w >> 1, wn = w & 1;

    const float* Ar0 = A + (size_t)(m0 + r0) * D + c4;
    const float* Ar1 = A + (size_t)(m0 + 64 + r0) * D + c4;
    const float* Wr0 = W + (size_t)(n0 + r0) * D + c4;

    float4 pa0, pa1, pb0;

#define PGLOAD(K0) do { \
        pa0 = *(const float4*)(Ar0 + (K0)); \
        pa1 = *(const float4*)(Ar1 + (K0)); \
        pb0 = *(const float4*)(Wr0 + (K0)); } while (0)

#define PGSTORE(BUF) do { \
        As[BUF][c4 + 0][r0] = f2tf32(pa0.x); As[BUF][c4 + 1][r0] = f2tf32(pa0.y); \
        As[BUF][c4 + 2][r0] = f2tf32(pa0.z); As[BUF][c4 + 3][r0] = f2tf32(pa0.w); \
        As[BUF][c4 + 0][64 + r0] = f2tf32(pa1.x); As[BUF][c4 + 1][64 + r0] = f2tf32(pa1.y); \
        As[BUF][c4 + 2][64 + r0] = f2tf32(pa1.z); As[BUF][c4 + 3][64 + r0] = f2tf32(pa1.w); \
        Bs[BUF][c4 + 0][r0] = f2tf32(pb0.x); Bs[BUF][c4 + 1][r0] = f2tf32(pb0.y); \
        Bs[BUF][c4 + 2][r0] = f2tf32(pb0.z); Bs[BUF][c4 + 3][r0] = f2tf32(pb0.w); } while (0)

    float c[2][4][4];
#pragma unroll
    for (int mt = 0; mt < 2; mt++)
#pragma unroll
        for (int nt = 0; nt < 4; nt++)
#pragma unroll
            for (int r = 0; r < 4; r++) c[mt][nt][r] = 0.f;

    PGLOAD(0);
    PGSTORE(0);
    __syncthreads();

    int buf = 0;
    for (int k0 = 0; k0 < D; k0 += 16) {
        const bool more = (k0 + 16 < D);
        if (more) PGLOAD(k0 + 16);
#pragma unroll
        for (int ks = 0; ks < 16; ks += 8) {
            const int kb = ks + tig;
            unsigned a[2][4], b[4][2];
#pragma unroll
            for (int mt = 0; mt < 2; mt++) {
                const int ma = wm * 32 + mt * 16 + g;
                a[mt][0] = As[buf][kb][ma];
                a[mt][1] = As[buf][kb][ma + 8];
                a[mt][2] = As[buf][kb + 4][ma];
                a[mt][3] = As[buf][kb + 4][ma + 8];
            }
#pragma unroll
            for (int nt = 0; nt < 4; nt++) {
                const int nb = wn * 32 + nt * 8 + g;
                b[nt][0] = Bs[buf][kb][nb];
                b[nt][1] = Bs[buf][kb + 4][nb];
            }
#pragma unroll
            for (int mt = 0; mt < 2; mt++)
#pragma unroll
                for (int nt = 0; nt < 4; nt++) MMA8(c[mt][nt], a[mt], b[nt]);
        }
        if (more) {
            buf ^= 1;
            PGSTORE(buf);
            __syncthreads();
        }
    }

#pragma unroll
    for (int mt = 0; mt < 2; mt++) {
        const int r = m0 + wm * 32 + mt * 16 + g;
#pragma unroll
        for (int nt = 0; nt < 4; nt++) {
            const int col = n0 + wn * 32 + nt * 8 + 2 * tig;
            const float b0v = bias[col], b1v = bias[col + 1];
            *(float2*)(Cm + (size_t)r * D + col) =
                make_float2(c[mt][nt][0] + b0v, c[mt][nt][1] + b1v);
            *(float2*)(Cm + (size_t)(r + 8) * D + col) =
                make_float2(c[mt][nt][2] + b0v, c[mt][nt][3] + b1v);
        }
    }
#undef PGLOAD
#undef PGSTORE
}

// ============================================================
// 64x64 tf32 mma core. If stage != nullptr, the tile is written
// to smem staging (local coords) instead of global. stage MAY
// alias As/Bs: it is only written after the final barrier.
// ============================================================
__device__ __forceinline__ void gemm64_tf32_core(
        const float* __restrict__ A, int lda,
        const float* __restrict__ B, int ldb,
        float* __restrict__ Cm, int ldc,
        const float* __restrict__ bias,
        int m0, int n0, int K,
        unsigned (*As)[72], unsigned (*Bs)[72],
        float (*stage)[68]) {
    const int tid = threadIdx.x;
    const int w = tid >> 5, lane = tid & 31;
    const int g = lane >> 2, tig = lane & 3;
    const int wm = w >> 1, wn = w & 1;
    const int lm = tid >> 1;
    const int lk8 = (tid & 1) * 8;

    float c[2][4][4];
#pragma unroll
    for (int mt = 0; mt < 2; mt++)
#pragma unroll
        for (int nt = 0; nt < 4; nt++)
#pragma unroll
            for (int r = 0; r < 4; r++) c[mt][nt][r] = 0.f;

    for (int k0 = 0; k0 < K; k0 += 16) {
        float4 xa = *(const float4*)(A + (size_t)(m0 + lm) * lda + k0 + lk8);
        float4 ya = *(const float4*)(A + (size_t)(m0 + lm) * lda + k0 + lk8 + 4);
        float4 xb = *(const float4*)(B + (size_t)(n0 + lm) * ldb + k0 + lk8);
        float4 yb = *(const float4*)(B + (size_t)(n0 + lm) * ldb + k0 + lk8 + 4);
        As[lk8 + 0][lm] = f2tf32(xa.x); As[lk8 + 1][lm] = f2tf32(xa.y);
        As[lk8 + 2][lm] = f2tf32(xa.z); As[lk8 + 3][lm] = f2tf32(xa.w);
        As[lk8 + 4][lm] = f2tf32(ya.x); As[lk8 + 5][lm] = f2tf32(ya.y);
        As[lk8 + 6][lm] = f2tf32(ya.z); As[lk8 + 7][lm] = f2tf32(ya.w);
        Bs[lk8 + 0][lm] = f2tf32(xb.x); Bs[lk8 + 1][lm] = f2tf32(xb.y);
        Bs[lk8 + 2][lm] = f2tf32(xb.z); Bs[lk8 + 3][lm] = f2tf32(xb.w);
        Bs[lk8 + 4][lm] = f2tf32(yb.x); Bs[lk8 + 5][lm] = f2tf32(yb.y);
        Bs[lk8 + 6][lm] = f2tf32(yb.z); Bs[lk8 + 7][lm] = f2tf32(yb.w);
        __syncthreads();
#pragma unroll
        for (int ks = 0; ks < 16; ks += 8) {
            const int kb = ks + tig;
            unsigned a[2][4], b[4][2];
#pragma unroll
            for (int mt = 0; mt < 2; mt++) {
                const int ma = wm * 32 + mt * 16 + g;
                a[mt][0] = As[kb][ma];
                a[mt][1] = As[kb][ma + 8];
                a[mt][2] = As[kb + 4][ma];
                a[mt][3] = As[kb + 4][ma + 8];
            }
#pragma unroll
            for (int nt = 0; nt < 4; nt++) {
                const int nb = wn * 32 + nt * 8 + g;
                b[nt][0] = Bs[kb][nb];
                b[nt][1] = Bs[kb + 4][nb];
            }
#pragma unroll
            for (int mt = 0; mt < 2; mt++)
#pragma unroll
                for (int nt = 0; nt < 4; nt++) MMA8(c[mt][nt], a[mt], b[nt]);
        }
        __syncthreads();
    }

    if (stage) {
#pragma unroll
        for (int mt = 0; mt < 2; mt++) {
            const int lr = wm * 32 + mt * 16 + g;
#pragma unroll
            for (int nt = 0; nt < 4; nt++) {
                const int col = wn * 32 + nt * 8 + 2 * tig;
                stage[lr][col + 0] = c[mt][nt][0];
                stage[lr][col + 1] = c[mt][nt][1];
                stage[lr + 8][col + 0] = c[mt][nt][2];
                stage[lr + 8][col + 1] = c[mt][nt][3];
            }
        }
        return;
    }

#pragma unroll
    for (int mt = 0; mt < 2; mt++) {
        const int r = m0 + wm * 32 + mt * 16 + g;
#pragma unroll
        for (int nt = 0; nt < 4; nt++) {
            const int col = n0 + wn * 32 + nt * 8 + 2 * tig;
            float b0v = 0.f, b1v = 0.f;
            if (bias) { b0v = bias[col]; b1v = bias[col + 1]; }
            *(float2*)(Cm + (size_t)r * ldc + col) =
                make_float2(c[mt][nt][0] + b0v, c[mt][nt][1] + b1v);
            *(float2*)(Cm + (size_t)(r + 8) * ldc + col) =
                make_float2(c[mt][nt][2] + b0v, c[mt][nt][3] + b1v);
        }
    }
}

// ============================================================
// scores (tf32): merged A/B/C head GEMMs, 64x64 tiles, pruned.
// Sc branch writes DIRECTLY to diagonal layout Cd. The staging
// buffer ALIASES As/Bs (union) — smem/block 26.6KB -> 17.4KB.
// ============================================================
__global__ __launch_bounds__(128) void scores_tf32_kernel(
        const float* __restrict__ qf, const float* __restrict__ kf,
        const float* __restrict__ rkt, const float* __restrict__ rqt,
        float* __restrict__ Sa, float* __restrict__ Sb, float* __restrict__ Cd) {
    const int h = blockIdx.y;
    int bi = blockIdx.x;
    const float *A, *B; float* Cm = nullptr; int m0, n0, ldc = 0;
    bool diag = false;

    if (bi < 64) {
        m0 = (bi >> 3) * 64; n0 = (bi & 7) * 64;
        A = qf; B = kf; Cm = Sa + (size_t)h * S * S; ldc = S;
    } else if (bi < 192) {
        bi -= 64;
        m0 = (bi >> 4) * 64; n0 = (bi & 15) * 64;
        const int sum = m0 + n0;
        if (sum + 126 < 512 || sum > 1023) return;
        A = qf; B = rkt; Cm = Sb + (size_t)h * S * NE; ldc = NE;
    } else {
        bi -= 192;
        m0 = (bi >> 3) * 64; n0 = (bi & 7) * 64;   // rows e, cols j
        const int d = m0 - n0;
        if (d < 0 || d > 512) return;
        A = rqt; B = kf; diag = true;
    }
    A += h * HD; B += h * HD;

    // union: [As(4.6KB) | Bs(4.6KB)] overlaid with st(17.4KB)
    __shared__ __align__(16) unsigned char smem_u[64 * 68 * 4];
    unsigned (*As)[72] = (unsigned(*)[72])smem_u;
    unsigned (*Bs)[72] = (unsigned(*)[72])(smem_u + 16 * 72 * 4);
    float (*st)[68] = (float(*)[68])smem_u;

    gemm64_tf32_core(A, D, B, D, Cm, ldc, nullptr, m0, n0, HD, As, Bs,
                     diag ? st : nullptr);

    if (diag) {
        __syncthreads();
        // tile rows are e (m0 base), cols are j (n0 base).
        // i = j - e + 512 ; diagonal dd = lj - le ; i = ib + dd.
        const int ib = 512 + n0 - m0;
        const int tid = threadIdx.x;
        const int sub = tid >> 6;       // 2 diagonals in parallel
        const int lj = tid & 63;
        float* CdH = Cd + (size_t)h * S * S;
#pragma unroll 8
        for (int rr = 0; rr < 128; rr += 2) {
            const int dd = rr + sub - 63;
            const int i = ib + dd;
            if (i >= 0 && i < S && lj >= dd && lj <= 63 + dd)
                CdH[(size_t)i * S + n0 + lj] = st[lj - dd][lj];
        }
    }
}

// ============================================================
// out-proj split-K2 (tf32): part[ks] = ctx[:,ks*256:+256] @ wo^T
// ============================================================
__global__ __launch_bounds__(128) void out_part_tf32_kernel(
        const float* __restrict__ ctx, const float* __restrict__ wo,
        float* __restrict__ part) {
    const int ks = blockIdx.z;
    __shared__ unsigned As[16][72];
    __shared__ unsigned Bs[16][72];
    gemm64_tf32_core(ctx + ks * 256, D, wo + ks * 256, D,
                     part + (size_t)ks * S * D, D, nullptr,
                     blockIdx.y * 64, blockIdx.x * 64, 256, As, Bs, nullptr);
}

__global__ void reduce2_bias_kernel(const float* __restrict__ part,
                                    const float* __restrict__ bias,
                                    float* __restrict__ dst) {
    const int idx = (blockIdx.x * 256 + threadIdx.x) * 4;
    float4 a = *(const float4*)(part + idx);
    float4 b = *(const float4*)(part + S * D + idx);
    float4 bi = *(const float4*)(bias + (idx & (D - 1)));
    *(float4*)(dst + idx) = make_float4(a.x + b.x + bi.x, a.y + b.y + bi.y,
                                        a.z + b.z + bi.z, a.w + b.w + bi.w);
}

// ============================================================
// warp-per-row softmax; all three score terms contiguous.
// ============================================================
__global__ __launch_bounds__(128) void softmax_warp_kernel(
        const float* __restrict__ Asc, const float* __restrict__ Bm,
        const float* __restrict__ Cd, float* __restrict__ attn) {
    const int h = blockIdx.y;
    const int warp = threadIdx.x >> 5, lane = threadIdx.x & 31;
    const int i = blockIdx.x * 4 + warp;

    const float* aRow = Asc + ((size_t)h * S + i) * S;
    const float* bRow = Bm + ((size_t)h * S + i) * NE + (512 - i);
    const float* cRow = Cd + ((size_t)h * S + i) * S;

    float sc[16];
#pragma unroll
    for (int t = 0; t < 16; t++) {
        const int j = t * 32 + lane;
        sc[t] = (aRow[j] + bRow[j] + cRow[j]) * 0.125f;
    }

    float mx = sc[0];
#pragma unroll
    for (int t = 1; t < 16; t++) mx = fmaxf(mx, sc[t]);
#pragma unroll
    for (int o = 16; o; o >>= 1) mx = fmaxf(mx, __shfl_xor_sync(0xffffffffu, mx, o));

    float sum = 0.f;
#pragma unroll
    for (int t = 0; t < 16; t++) {
        sc[t] = __expf(sc[t] - mx);
        sum += sc[t];
    }
#pragma unroll
    for (int o = 16; o; o >>= 1) sum += __shfl_xor_sync(0xffffffffu, sum, o);
    const float inv = 1.f / sum;

    float* oRow = attn + ((size_t)h * S + i) * S;
#pragma unroll
    for (int t = 0; t < 16; t++) oRow[t * 32 + lane] = sc[t] * inv;
}

// ============================================================
// ctx split-K8 (fp32 FFMA): 64x64 tile, float4 fragment loads.
// ============================================================
__global__ __launch_bounds__(256) void ctx_part_kernel(
        const float* __restrict__ attn, const float* __restrict__ vf,
        float* __restrict__ part) {
    const int mt = blockIdx.x, ks = blockIdx.y, h = blockIdx.z;
    const int m0 = mt * 64;
    const float* A = attn + (size_t)h * S * S;
    const float* B = vf + h * HD;

    __shared__ float As[16][68];
    __shared__ float Bs[16][68];

    const int tid = threadIdx.x;
    const int tx = tid & 15, ty = tid >> 4;
    const int lm = tid >> 2, lk = (tid & 3) * 4;
    const int rk = tid >> 4, nc4 = (tid & 15) * 4;

    float acc[4][4];
#pragma unroll
    for (int i = 0; i < 4; i++)
#pragma unroll
        for (int j = 0; j < 4; j++) acc[i][j] = 0.f;

    const int kbeg = ks * 64;
#pragma unroll 1
    for (int k0 = kbeg; k0 < kbeg + 64; k0 += 16) {
        float4 av = *(const float4*)(A + (size_t)(m0 + lm) * S + k0 + lk);
        As[lk + 0][lm] = av.x; As[lk + 1][lm] = av.y;
        As[lk + 2][lm] = av.z; As[lk + 3][lm] = av.w;
        float4 bv = *(const float4*)(B + (size_t)(k0 + rk) * D + nc4);
        *(float4*)&Bs[rk][nc4] = bv;
        __syncthreads();
#pragma unroll
        for (int kk = 0; kk < 16; kk++) {
            float4 a4 = *(const float4*)&As[kk][ty * 4];
            float4 b4 = *(const float4*)&Bs[kk][tx * 4];
            float a[4] = {a4.x, a4.y, a4.z, a4.w};
            float b[4] = {b4.x, b4.y, b4.z, b4.w};
#pragma unroll
            for (int i = 0; i < 4; i++)
#pragma unroll
                for (int j = 0; j < 4; j++) acc[i][j] += a[i] * b[j];
        }
        __syncthreads();
    }

    float* Cm = part + (size_t)ks * S * D + h * HD;
#pragma unroll
    for (int i = 0; i < 4; i++) {
        const int m = m0 + ty * 4 + i;
        *(float4*)(Cm + (size_t)m * D + tx * 4) =
            make_float4(acc[i][0], acc[i][1], acc[i][2], acc[i][3]);
    }
}

__global__ void reduce8_kernel(const float* __restrict__ part, float* __restrict__ dst) {
    const int idx = (blockIdx.x * 256 + threadIdx.x) * 4;
    float4 r = *(const float4*)(part + idx);
#pragma unroll
    for (int p = 1; p < 8; p++) {
        float4 x = *(const float4*)(part + (size_t)p * S * D + idx);
        r.x += x.x; r.y += x.y; r.z += x.z; r.w += x.w;
    }
    *(float4*)(dst + idx) = r;
}

extern "C" void kernel_launch(void* const* d_in, const int* in_sizes, int n_in,
                              void* d_out, int out_size) {
    const float* hs  = (const float*)d_in[0];
    const float* emb = (const float*)d_in[1];
    const float* wq  = (const float*)d_in[2];
    const float* bq  = (const float*)d_in[3];
    const float* wk  = (const float*)d_in[4];
    const float* bk  = (const float*)d_in[5];
    const float* wv  = (const float*)d_in[6];
    const float* bv  = (const float*)d_in[7];
    const float* wrk = (const float*)d_in[8];
    const float* brk = (const float*)d_in[9];
    const float* wrq = (const float*)d_in[10];
    const float* brq = (const float*)d_in[11];
    const float* wo  = (const float*)d_in[12];
    const float* bo  = (const float*)d_in[13];

    float* out  = (float*)d_out;
    float* attn = out + (size_t)S * D;

    float *q, *k, *v, *rkt, *rqt, *ctx, *Asc, *Bm, *Cd, *part;
    cudaGetSymbolAddress((void**)&q,    g_q);
    cudaGetSymbolAddress((void**)&k,    g_k);
    cudaGetSymbolAddress((void**)&v,    g_v);
    cudaGetSymbolAddress((void**)&rkt,  g_rkt);
    cudaGetSymbolAddress((void**)&rqt,  g_rqt);
    cudaGetSymbolAddress((void**)&ctx,  g_ctx);
    cudaGetSymbolAddress((void**)&Asc,  g_A);
    cudaGetSymbolAddress((void**)&Bm,   g_B);
    cudaGetSymbolAddress((void**)&Cd,   g_Cd);
    cudaGetSymbolAddress((void**)&part, g_part);

    // 1. fused projections (tf32, 128x64 tiles, 224 live blocks)
    proj_tf32_kernel<<<dim3(8, 8, 5), 256>>>(hs, emb, wq, bq, wk, bk, wv, bv,
                                             wrk, brk, wrq, brq, q, k, v, rkt, rqt);

    // 2. score GEMMs (tf32); Sc direct-to-diagonal; smem union
    scores_tf32_kernel<<<dim3(320, H), 128>>>(q, k, rkt, rqt, Asc, Bm, Cd);

    // 3. warp-per-row softmax -> attn (in d_out)
    softmax_warp_kernel<<<dim3(S / 4, H), 128>>>(Asc, Bm, Cd, attn);

    // 4. ctx split-K8 (512 blocks) + reduce
    ctx_part_kernel<<<dim3(8, 8, H), 256>>>(attn, v, part);
    reduce8_kernel<<<256, 256>>>(part, ctx);

    // 5. out projection split-K2 (128 blocks) + bias reduce
    out_part_tf32_kernel<<<dim3(8, 8, 2), 128>>>(ctx, wo, part);
    reduce2_bias_kernel<<<256, 256>>>(part, bo, out);
}